// round 5
// baseline (speedup 1.0000x reference)
#include <cuda_runtime.h>

typedef unsigned long long ull;

#define SEQ   512
#define HD    64
#define G4    256          // 4*H
#define ROWS  16           // batch rows per CTA
#define NCTA  128          // 2048 / 16
#define NTHR  256
#define OUTF  72
#define XP    18           // Xd pitch in ull (16B-aligned, bank-rotating)

// SMEM: W0s[64][256] | W1s[128][256] (f32, gate-interleaved cols)
//       Xd: h0 buf0 [64][XP] | h0 buf1 [64][XP] | h1 [64][XP] | pad [2][XP]
// Tail pad absorbs the software-pipeline prefetch over-reads (k+2/k+3 at loop end).
#define XD_ROWS (3*64 + 2)
#define SMEM_BYTES ((64*G4 + 128*G4)*4 + XD_ROWS*XP*8)   // 224544

__device__ __forceinline__ ull pack2(float a, float b) {
    ull r; asm("mov.b64 %0, {%1, %2};" : "=l"(r) : "f"(a), "f"(b)); return r;
}
__device__ __forceinline__ void unpack2(ull v, float &a, float &b) {
    asm("mov.b64 {%0, %1}, %2;" : "=f"(a), "=f"(b) : "l"(v));
}
__device__ __forceinline__ void fma2(ull &d, ull a, ull b) {
    asm("fma.rn.f32x2 %0, %1, %2, %0;" : "+l"(d) : "l"(a), "l"(b));
}
__device__ __forceinline__ float sigf(float x) {
    return __fdividef(1.0f, 1.0f + __expf(-x));
}
__device__ __forceinline__ float tanhf_(float x) {
    float e = __expf(-2.0f * fabsf(x));
    float r = __fdividef(1.0f - e, 1.0f + e);
    return copysignf(r, x);
}
__device__ __forceinline__ float cell_update(ull aIF, ull aGO, float &c) {
    float gi, gf, gg, go;
    unpack2(aIF, gi, gf);
    unpack2(aGO, gg, go);
    float i = sigf(gi), f = sigf(gf), g = tanhf_(gg), o = sigf(go);
    c = f * c + i * g;
    return o * tanhf_(c);
}

// 8 packed FMAs: one k-slice into the 8 accumulators
#define FMA8(hA, hB, wv)                                     \
    do {                                                     \
        fma2(aIF0, (hA).x, (wv).x); fma2(aGO0, (hA).x, (wv).y); \
        fma2(aIF1, (hA).y, (wv).x); fma2(aGO1, (hA).y, (wv).y); \
        fma2(aIF2, (hB).x, (wv).x); fma2(aGO2, (hB).x, (wv).y); \
        fma2(aIF3, (hB).y, (wv).x); fma2(aGO3, (hB).y, (wv).y); \
    } while (0)

// Distance-2 software-pipelined GEMM over NK k-slices.
// Hbase: ull* (dup-packed h, pitch XP). Wbase: float* (gate-interleaved, pitch G4).
// Over-reads 2 k-slices past the end (in-bounds garbage, discarded).
#define GEMM_PIPE(Hbase, Wbase, NK)                                             \
    do {                                                                        \
        const ull*   Hp = (Hbase);                                              \
        const float* Wp = (Wbase);                                              \
        ulonglong2 h0A = *(const ulonglong2*)&Hp[0 * XP + gr0];                 \
        ulonglong2 h2A = *(const ulonglong2*)&Hp[0 * XP + gr0 + 2];             \
        ulonglong2 wA  = *(const ulonglong2*)&Wp[0 * G4 + jc4];                 \
        ulonglong2 h0B = *(const ulonglong2*)&Hp[1 * XP + gr0];                 \
        ulonglong2 h2B = *(const ulonglong2*)&Hp[1 * XP + gr0 + 2];             \
        ulonglong2 wB  = *(const ulonglong2*)&Wp[1 * G4 + jc4];                 \
        _Pragma("unroll 8")                                                     \
        for (int k = 0; k < (NK); k += 2) {                                     \
            ulonglong2 nh0A = *(const ulonglong2*)&Hp[(k + 2) * XP + gr0];      \
            ulonglong2 nh2A = *(const ulonglong2*)&Hp[(k + 2) * XP + gr0 + 2];  \
            ulonglong2 nwA  = *(const ulonglong2*)&Wp[(k + 2) * G4 + jc4];      \
            ulonglong2 nh0B = *(const ulonglong2*)&Hp[(k + 3) * XP + gr0];      \
            ulonglong2 nh2B = *(const ulonglong2*)&Hp[(k + 3) * XP + gr0 + 2];  \
            ulonglong2 nwB  = *(const ulonglong2*)&Wp[(k + 3) * G4 + jc4];      \
            FMA8(h0A, h2A, wA);                                                 \
            FMA8(h0B, h2B, wB);                                                 \
            h0A = nh0A; h2A = nh2A; wA = nwA;                                   \
            h0B = nh0B; h2B = nh2B; wB = nwB;                                   \
        }                                                                       \
    } while (0)

__global__ __launch_bounds__(NTHR, 1)
void lstm_forecaster_kernel(const float* __restrict__ x,
                            const float* __restrict__ Wih0,
                            const float* __restrict__ Whh0,
                            const float* __restrict__ bih0,
                            const float* __restrict__ bhh0,
                            const float* __restrict__ Wih1,
                            const float* __restrict__ Whh1,
                            const float* __restrict__ bih1,
                            const float* __restrict__ bhh1,
                            const float* __restrict__ fcw,
                            const float* __restrict__ fcb,
                            float* __restrict__ out)
{
    extern __shared__ float sm[];
    float* W0s = sm;                           // [64][256]  gate-interleaved, k-major
    float* W1s = sm + 64 * G4;                 // [128][256] k<64: Wih1, k>=64: Whh1
    ull*   Xd  = (ull*)(sm + (64 + 128) * G4); // [XD_ROWS][XP]

    const int tid  = threadIdx.x;
    const int warp = tid >> 5, lane = tid & 31;
    const int rr   = lane >> 3;               // row-group 0..3
    const int gg   = lane & 7;                // cell-within-warp 0..7
    const int j    = warp * 8 + gg;           // cell index 0..63
    const int jc4  = j << 2;                  // first interleaved col of cell j
    const int gr0  = rr << 2;                 // first of 4 rows

    // ---- weights into shared, gate-interleaved: col' = cell*4 + gate ----
    for (int idx = tid; idx < 64 * G4; idx += NTHR) {
        int k = idx >> 8, col = idx & 255;
        int jj = col >> 2, g = col & 3;
        W0s[idx] = Whh0[(g * HD + jj) * HD + k];
    }
    for (int idx = tid; idx < 128 * G4; idx += NTHR) {
        int k = idx >> 8, col = idx & 255;
        int jj = col >> 2, g = col & 3;
        W1s[idx] = (k < HD) ? Wih1[(g * HD + jj) * HD + k]
                            : Whh1[(g * HD + jj) * HD + (k - HD)];
    }
    for (int idx = tid; idx < XD_ROWS * XP; idx += NTHR) Xd[idx] = 0ull;

    // ---- per-thread constants for cell j ----
    ull w0if = pack2(Wih0[j],          Wih0[j + HD]);
    ull w0go = pack2(Wih0[j + 2*HD],   Wih0[j + 3*HD]);
    ull b0if = pack2(bih0[j] + bhh0[j],               bih0[j + HD] + bhh0[j + HD]);
    ull b0go = pack2(bih0[j + 2*HD] + bhh0[j + 2*HD], bih0[j + 3*HD] + bhh0[j + 3*HD]);
    ull b1if = pack2(bih1[j] + bhh1[j],               bih1[j + HD] + bhh1[j + HD]);
    ull b1go = pack2(bih1[j + 2*HD] + bhh1[j + 2*HD], bih1[j + 3*HD] + bhh1[j + 3*HD]);

    float c0[4] = {0.f, 0.f, 0.f, 0.f};
    float c1[4] = {0.f, 0.f, 0.f, 0.f};

    ull* X0a = Xd + 64 * XP;   // read at s=0 (zeros)
    ull* X0b = Xd;             // written at s=0
    ull* X1  = Xd + 2 * 64 * XP;

    const int gRow = blockIdx.x * ROWS;

    float xr0 = x[(gRow + gr0 + 0) * SEQ];
    float xr1 = x[(gRow + gr0 + 1) * SEQ];
    float xr2 = x[(gRow + gr0 + 2) * SEQ];
    float xr3 = x[(gRow + gr0 + 3) * SEQ];

    __syncthreads();

    for (int s = 0; s < SEQ; ++s) {
        ull* X0r = X0a;   // h0(s-1)
        ull* X0w = X0b;   // receives h0(s)

        // ============ layer 0: gates = b0 + x*wih0 + h0(s-1) @ Whh0^T ============
        ull aIF0 = b0if, aGO0 = b0go, aIF1 = b0if, aGO1 = b0go;
        ull aIF2 = b0if, aGO2 = b0go, aIF3 = b0if, aGO3 = b0go;
        {
            ull xx0 = pack2(xr0, xr0), xx1 = pack2(xr1, xr1);
            ull xx2 = pack2(xr2, xr2), xx3 = pack2(xr3, xr3);
            fma2(aIF0, xx0, w0if); fma2(aGO0, xx0, w0go);
            fma2(aIF1, xx1, w0if); fma2(aGO1, xx1, w0go);
            fma2(aIF2, xx2, w0if); fma2(aGO2, xx2, w0go);
            fma2(aIF3, xx3, w0if); fma2(aGO3, xx3, w0go);
        }
        int sn = (s + 1 < SEQ) ? (s + 1) : s;
        float xn0 = x[(gRow + gr0 + 0) * SEQ + sn];
        float xn1 = x[(gRow + gr0 + 1) * SEQ + sn];
        float xn2 = x[(gRow + gr0 + 2) * SEQ + sn];
        float xn3 = x[(gRow + gr0 + 3) * SEQ + sn];

        GEMM_PIPE(X0r, W0s, HD);

        xr0 = xn0; xr1 = xn1; xr2 = xn2; xr3 = xn3;

        // ============ layer 0 state update -> h0(s) into X0w (double buffer) ============
        {
            float h0 = cell_update(aIF0, aGO0, c0[0]);
            float h1 = cell_update(aIF1, aGO1, c0[1]);
            float h2 = cell_update(aIF2, aGO2, c0[2]);
            float h3 = cell_update(aIF3, aGO3, c0[3]);
            *(ulonglong2*)&X0w[j * XP + gr0]     = make_ulonglong2(pack2(h0, h0), pack2(h1, h1));
            *(ulonglong2*)&X0w[j * XP + gr0 + 2] = make_ulonglong2(pack2(h2, h2), pack2(h3, h3));
        }
        __syncthreads();   // h0(s) + h1(s-1) visible to all

        // ============ layer 1: gates = b1 + h0(s)@Wih1^T + h1(s-1)@Whh1^T ============
        aIF0 = b1if; aGO0 = b1go; aIF1 = b1if; aGO1 = b1go;
        aIF2 = b1if; aGO2 = b1go; aIF3 = b1if; aGO3 = b1go;

        GEMM_PIPE(X0w, W1s, HD);
        GEMM_PIPE(X1,  W1s + HD * G4, HD);

        __syncthreads();   // WAR: all h1(s-1) reads done before overwrite

        // ============ layer 1 state update -> h1(s) (overlaps next L0 GEMM) ============
        {
            float h0 = cell_update(aIF0, aGO0, c1[0]);
            float h1 = cell_update(aIF1, aGO1, c1[1]);
            float h2 = cell_update(aIF2, aGO2, c1[2]);
            float h3 = cell_update(aIF3, aGO3, c1[3]);
            *(ulonglong2*)&X1[j * XP + gr0]     = make_ulonglong2(pack2(h0, h0), pack2(h1, h1));
            *(ulonglong2*)&X1[j * XP + gr0 + 2] = make_ulonglong2(pack2(h2, h2), pack2(h3, h3));
        }

        ull* t = X0a; X0a = X0b; X0b = t;
    }

    __syncthreads();

    // ============ final FC: out = h1_last @ fcw^T + fcb ============
    const float* H1 = (const float*)(Xd + 2 * 64 * XP);
    for (int idx = tid; idx < ROWS * OUTF; idx += NTHR) {
        int r = idx / OUTF;
        int o = idx - r * OUTF;
        float acc = fcb[o];
        #pragma unroll 16
        for (int k = 0; k < HD; ++k) {
            float h = H1[(k * XP + r) * 2];
            acc = fmaf(h, fcw[o * HD + k], acc);
        }
        out[(gRow + r) * OUTF + o] = acc;
    }
}

extern "C" void kernel_launch(void* const* d_in, const int* in_sizes, int n_in,
                              void* d_out, int out_size)
{
    (void)in_sizes; (void)n_in; (void)out_size;
    cudaFuncSetAttribute(lstm_forecaster_kernel,
                         cudaFuncAttributeMaxDynamicSharedMemorySize, SMEM_BYTES);
    lstm_forecaster_kernel<<<NCTA, NTHR, SMEM_BYTES>>>(
        (const float*)d_in[0],   // x
        (const float*)d_in[1],   // W_ih_l0
        (const float*)d_in[2],   // W_hh_l0
        (const float*)d_in[3],   // b_ih_l0
        (const float*)d_in[4],   // b_hh_l0
        (const float*)d_in[5],   // W_ih_l1
        (const float*)d_in[6],   // W_hh_l1
        (const float*)d_in[7],   // b_ih_l1
        (const float*)d_in[8],   // b_hh_l1
        (const float*)d_in[9],   // fc_w
        (const float*)d_in[10],  // fc_b
        (float*)d_out);
}

// round 7
// speedup vs baseline: 2.5512x; 2.5512x over previous
#include <cuda_runtime.h>
#include <cuda_bf16.h>
#include <cstdint>

#define SEQ  512
#define NTHR 256
#define NCTA 128
#define OUTF 72
#define GXP  20

// ---- SMEM map (bytes) ----
#define OFF_W0H 0           // Whh0 [256 n][64 k] bf16 hi, SW128 (32KB)
#define OFF_W0L 32768
#define OFF_W1H 65536       // blk0 = Wih1, blk1 = Whh1, each [256][64] bf16 (64KB)
#define OFF_W1L 131072
#define OFF_A0  196608      // h0 tiles: H0,L0,H1,L1 each [16][64] bf16 = 2048B
#define OFF_A1H 204800      // h1 tile hi
#define OFF_A1L 206848
#define OFF_GX  208896      // gate exchange [256 n][GXP m] f32 (20480B)
#define OFF_XS  229376      // x chunk [16 m][32 s] f32 (2048B)
#define SMEM_BYTES 231424
#define OFF_H1F 0           // aliases W0H after its last use; [16][68] f32

#define SW128(o) ((o) ^ (((o) >> 3) & 0x70))

__device__ __forceinline__ uint32_t smem_u32(const void* p) {
    uint32_t a;
    asm("{ .reg .u64 t; cvta.to.shared.u64 t, %1; cvt.u32.u64 %0, t; }" : "=r"(a) : "l"(p));
    return a;
}
__device__ __forceinline__ void ldsm4(uint32_t addr, uint32_t r[4]) {
    asm volatile("ldmatrix.sync.aligned.m8n8.x4.shared.b16 {%0,%1,%2,%3}, [%4];"
                 : "=r"(r[0]), "=r"(r[1]), "=r"(r[2]), "=r"(r[3]) : "r"(addr));
}
__device__ __forceinline__ void mma_bf16(float d[4], const uint32_t a[4],
                                         uint32_t b0, uint32_t b1) {
    asm("mma.sync.aligned.m16n8k16.row.col.f32.bf16.bf16.f32 "
        "{%0,%1,%2,%3}, {%4,%5,%6,%7}, {%8,%9}, {%0,%1,%2,%3};"
        : "+f"(d[0]), "+f"(d[1]), "+f"(d[2]), "+f"(d[3])
        : "r"(a[0]), "r"(a[1]), "r"(a[2]), "r"(a[3]), "r"(b0), "r"(b1));
}
__device__ __forceinline__ float sigf(float v) {
    return __fdividef(1.0f, 1.0f + __expf(-v));
}
__device__ __forceinline__ float tanhf_(float v) {
    float e = __expf(-2.0f * fabsf(v));
    return copysignf(__fdividef(1.0f - e, 1.0f + e), v);
}
__device__ __forceinline__ void bfsplit(float v, __nv_bfloat16& hi, __nv_bfloat16& lo) {
    hi = __float2bfloat16(v);
    lo = __float2bfloat16(v - __bfloat162float(hi));
}

// 2-split bf16 MMA block: one 16-wide k-chunk vs 2 n8-tile-pairs (12 MMAs)
#define MMA_KC(d, aH, aL, wH, wL, nt2base, colB)                                 \
    do {                                                                         \
        uint32_t bh[4], bl[4];                                                   \
        ldsm4((wH) + (nt2base) + (colB), bh);                                    \
        ldsm4((wL) + (nt2base) + (colB), bl);                                    \
        int _t = ((nt2base) ? 2 : 0);                                            \
        mma_bf16(d[_t],     aH, bh[0], bh[1]);                                   \
        mma_bf16(d[_t],     aH, bl[0], bl[1]);                                   \
        mma_bf16(d[_t],     aL, bh[0], bh[1]);                                   \
        mma_bf16(d[_t + 1], aH, bh[2], bh[3]);                                   \
        mma_bf16(d[_t + 1], aH, bl[2], bl[3]);                                   \
        mma_bf16(d[_t + 1], aL, bh[2], bh[3]);                                   \
    } while (0)

__global__ __launch_bounds__(NTHR, 1)
void lstm_mma_kernel(const float* __restrict__ x,
                     const float* __restrict__ Wih0, const float* __restrict__ Whh0,
                     const float* __restrict__ bih0, const float* __restrict__ bhh0,
                     const float* __restrict__ Wih1, const float* __restrict__ Whh1,
                     const float* __restrict__ bih1, const float* __restrict__ bhh1,
                     const float* __restrict__ fcw,  const float* __restrict__ fcb,
                     float* __restrict__ out)
{
    extern __shared__ char smem[];
    const uint32_t sb = smem_u32(smem);
    const int tid = threadIdx.x, warp = tid >> 5, lane = tid & 31;
    const int j = tid >> 2, p = tid & 3;     // epilogue: cell, batch-quad
    const int r8 = lane & 7, mid = lane >> 3;

    // ldmatrix per-lane address components (A-tiles and B-tiles, SW128, 128B rows)
    const uint32_t swz  = (uint32_t)(r8 << 4);
    const uint32_t aRow = (uint32_t)((r8 + ((mid & 1) << 3)) * 128);
    const uint32_t aK2  = (uint32_t)((mid & 2) << 3);          // 0 or 16
    const uint32_t bRow = (uint32_t)((r8 + ((mid & 2) << 2)) * 128);
    const uint32_t bK2  = (uint32_t)((mid & 1) << 4);          // 0 or 16

    // ---- load weights: natural [n][k] bf16 hi/lo, SW128 ----
    for (int idx = tid; idx < 256 * 64; idx += NTHR) {
        int n = idx >> 6, k = idx & 63;
        __nv_bfloat16 hi, lo;
        bfsplit(Whh0[n * 64 + k], hi, lo);
        uint32_t off = SW128((uint32_t)(n * 128 + k * 2));
        *(__nv_bfloat16*)(smem + OFF_W0H + off) = hi;
        *(__nv_bfloat16*)(smem + OFF_W0L + off) = lo;
    }
    for (int idx = tid; idx < 2 * 256 * 64; idx += NTHR) {
        int blk = idx >> 14, rem = idx & 16383;
        int n = rem >> 6, k = rem & 63;
        float v = blk ? Whh1[n * 64 + k] : Wih1[n * 64 + k];
        __nv_bfloat16 hi, lo;
        bfsplit(v, hi, lo);
        uint32_t off = (uint32_t)(blk * 32768) + SW128((uint32_t)(n * 128 + k * 2));
        *(__nv_bfloat16*)(smem + OFF_W1H + off) = hi;
        *(__nv_bfloat16*)(smem + OFF_W1L + off) = lo;
    }
    // zero h tiles (A0 x2 bufs + A1: 12KB)
    for (int idx = tid; idx < 12288 / 4; idx += NTHR)
        ((uint32_t*)(smem + OFF_A0))[idx] = 0;

    // per-thread scalars (cell j)
    float b0[4], w0[4], b1[4];
#pragma unroll
    for (int g = 0; g < 4; ++g) {
        b0[g] = bih0[g * 64 + j] + bhh0[g * 64 + j];
        w0[g] = Wih0[g * 64 + j];
        b1[g] = bih1[g * 64 + j] + bhh1[g * 64 + j];
    }
    float c0[4] = {0.f, 0.f, 0.f, 0.f}, c1[4] = {0.f, 0.f, 0.f, 0.f};

    const uint32_t uW0H = sb + OFF_W0H + warp * 4096;   // warp's 32 n-rows
    const uint32_t uW0L = sb + OFF_W0L + warp * 4096;
    const uint32_t uW1H = sb + OFF_W1H + warp * 4096;
    const uint32_t uW1L = sb + OFF_W1L + warp * 4096;
    float* gxf = (float*)(smem + OFF_GX);
    float* xs  = (float*)(smem + OFF_XS);
    const int gRow = blockIdx.x * 16;
    const int m0 = lane >> 2, nc0 = (lane & 3) * 2;     // D-frag coords

    __syncthreads();

    for (int s = 0; s < SEQ; ++s) {
        if ((s & 31) == 0) {   // refill x chunk: xs[m][sc] = x[gRow+m][s+sc]
            for (int q = tid; q < 512; q += NTHR)
                xs[q] = x[(size_t)(gRow + (q >> 5)) * SEQ + s + (q & 31)];
            __syncthreads();
        }
        const int rb = s & 1;
        const uint32_t A0rH = sb + OFF_A0 + rb * 4096;          // h0(s-1) hi
        const uint32_t A0rL = A0rH + 2048;
        const uint32_t A0wH = sb + OFF_A0 + (1 - rb) * 4096;    // h0(s) dest
        const uint32_t A0wL = A0wH + 2048;

        // ================= layer 0 MMA: D = h0(s-1) @ Whh0^T =================
        float d[4][4];
#pragma unroll
        for (int t = 0; t < 4; ++t) d[t][0] = d[t][1] = d[t][2] = d[t][3] = 0.f;
#pragma unroll
        for (int kc = 0; kc < 4; ++kc) {
            uint32_t colA = ((uint32_t)(kc * 32) + aK2) ^ swz;
            uint32_t colB = ((uint32_t)(kc * 32) + bK2) ^ swz;
            uint32_t ah[4], al[4];
            ldsm4(A0rH + aRow + colA, ah);
            ldsm4(A0rL + aRow + colA, al);
            MMA_KC(d, ah, al, uW0H + bRow, uW0L + bRow, 0, colB);
            MMA_KC(d, ah, al, uW0H + bRow, uW0L + bRow, 2048, colB);
        }
        // write D to gate exchange [n][m]
#pragma unroll
        for (int nt = 0; nt < 4; ++nt) {
            int n = warp * 32 + nt * 8 + nc0;
            gxf[n * GXP + m0]           = d[nt][0];
            gxf[(n + 1) * GXP + m0]     = d[nt][1];
            gxf[n * GXP + m0 + 8]       = d[nt][2];
            gxf[(n + 1) * GXP + m0 + 8] = d[nt][3];
        }
        __syncthreads();
        // ---- layer 0 epilogue: cell update, h0(s) -> A0w tiles ----
        {
            float G[4][4];
#pragma unroll
            for (int g = 0; g < 4; ++g)
                *(float4*)&G[g][0] = *(const float4*)&gxf[(g * 64 + j) * GXP + 4 * p];
#pragma unroll
            for (int i = 0; i < 4; ++i) {
                float xi = xs[(4 * p + i) * 32 + (s & 31)];
                float vi = G[0][i] + b0[0] + w0[0] * xi;
                float vf = G[1][i] + b0[1] + w0[1] * xi;
                float vg = G[2][i] + b0[2] + w0[2] * xi;
                float vo = G[3][i] + b0[3] + w0[3] * xi;
                float ii = sigf(vi), ff = sigf(vf), tg = tanhf_(vg), oo = sigf(vo);
                c0[i] = ff * c0[i] + ii * tg;
                float h = oo * tanhf_(c0[i]);
                int m = 4 * p + i;
                uint32_t off = (uint32_t)(m * 128 + j * 2) ^ (uint32_t)((m & 7) << 4);
                __nv_bfloat16 hi, lo;
                bfsplit(h, hi, lo);
                *(__nv_bfloat16*)(smem + (A0wH - sb) + off) = hi;
                *(__nv_bfloat16*)(smem + (A0wL - sb) + off) = lo;
            }
        }
        __syncthreads();

        // ========== layer 1 MMA: D = h0(s) @ Wih1^T + h1(s-1) @ Whh1^T ==========
#pragma unroll
        for (int t = 0; t < 4; ++t) d[t][0] = d[t][1] = d[t][2] = d[t][3] = 0.f;
#pragma unroll
        for (int kc = 0; kc < 8; ++kc) {
            int kcc = kc & 3;
            uint32_t aT = (kc < 4) ? A0wH : (sb + OFF_A1H);
            uint32_t colA = ((uint32_t)(kcc * 32) + aK2) ^ swz;
            uint32_t colB = ((uint32_t)(kcc * 32) + bK2) ^ swz;
            uint32_t wH = ((kc < 4) ? uW1H : uW1H + 32768) + bRow;
            uint32_t wL = ((kc < 4) ? uW1L : uW1L + 32768) + bRow;
            uint32_t ah[4], al[4];
            ldsm4(aT + aRow + colA, ah);
            ldsm4(aT + 2048 + aRow + colA, al);
            MMA_KC(d, ah, al, wH, wL, 0, colB);
            MMA_KC(d, ah, al, wH, wL, 2048, colB);
        }
#pragma unroll
        for (int nt = 0; nt < 4; ++nt) {
            int n = warp * 32 + nt * 8 + nc0;
            gxf[n * GXP + m0]           = d[nt][0];
            gxf[(n + 1) * GXP + m0]     = d[nt][1];
            gxf[n * GXP + m0 + 8]       = d[nt][2];
            gxf[(n + 1) * GXP + m0 + 8] = d[nt][3];
        }
        __syncthreads();
        // ---- layer 1 epilogue: cell update, h1(s) -> A1 tiles ----
        {
            float G[4][4];
#pragma unroll
            for (int g = 0; g < 4; ++g)
                *(float4*)&G[g][0] = *(const float4*)&gxf[(g * 64 + j) * GXP + 4 * p];
#pragma unroll
            for (int i = 0; i < 4; ++i) {
                float vi = G[0][i] + b1[0];
                float vf = G[1][i] + b1[1];
                float vg = G[2][i] + b1[2];
                float vo = G[3][i] + b1[3];
                float ii = sigf(vi), ff = sigf(vf), tg = tanhf_(vg), oo = sigf(vo);
                c1[i] = ff * c1[i] + ii * tg;
                float h = oo * tanhf_(c1[i]);
                int m = 4 * p + i;
                uint32_t off = (uint32_t)(m * 128 + j * 2) ^ (uint32_t)((m & 7) << 4);
                __nv_bfloat16 hi, lo;
                bfsplit(h, hi, lo);
                *(__nv_bfloat16*)(smem + OFF_A1H + off) = hi;
                *(__nv_bfloat16*)(smem + OFF_A1L + off) = lo;
                if (s == SEQ - 1)
                    ((float*)(smem + OFF_H1F))[m * 68 + j] = h;   // aliases dead W0H
            }
        }
        __syncthreads();
    }

    // ================= final FC: out = h1(S-1) @ fcw^T + fcb =================
    const float* h1f = (const float*)(smem + OFF_H1F);
    for (int idx = tid; idx < 16 * OUTF; idx += NTHR) {
        int r = idx / OUTF, o = idx - r * OUTF;
        float acc = fcb[o];
#pragma unroll 16
        for (int k = 0; k < 64; ++k)
            acc = fmaf(h1f[r * 68 + k], fcw[o * 64 + k], acc);
        out[(gRow + r) * OUTF + o] = acc;
    }
}

extern "C" void kernel_launch(void* const* d_in, const int* in_sizes, int n_in,
                              void* d_out, int out_size)
{
    (void)in_sizes; (void)n_in; (void)out_size;
    cudaFuncSetAttribute(lstm_mma_kernel,
                         cudaFuncAttributeMaxDynamicSharedMemorySize, SMEM_BYTES);
    lstm_mma_kernel<<<NCTA, NTHR, SMEM_BYTES>>>(
        (const float*)d_in[0],  (const float*)d_in[1],  (const float*)d_in[2],
        (const float*)d_in[3],  (const float*)d_in[4],  (const float*)d_in[5],
        (const float*)d_in[6],  (const float*)d_in[7],  (const float*)d_in[8],
        (const float*)d_in[9],  (const float*)d_in[10], (float*)d_out);
}

// round 8
// speedup vs baseline: 3.5736x; 1.4008x over previous
#include <cuda_runtime.h>
#include <cuda_fp16.h>
#include <cstdint>

#define SEQ  512
#define NTHR 256
#define NCTA 128
#define OUTF 72

// ---- SMEM map (bytes) ----
// Weights fp16, gate-interleaved cols n' = cell*4 + gate, [256 n'][64 k], 128B rows, SW128
#define OFF_W0H 0           // Whh0 hi (32KB)
#define OFF_W0L 32768       // Whh0 lo
#define OFF_W1H 65536       // blk0 = Wih1, blk1 = Whh1 (at +32768), hi (64KB)
#define OFF_W1L 131072      // lo (64KB)
#define OFF_A0  196608      // h0 fp16 tiles [16 m][64 cell], 2 buffers x 2KB
#define OFF_A1  200704      // h1 fp16 tile (2KB)
#define OFF_XS  202752      // x chunk [32 s][16 m] f32 (2KB)
#define OFF_H1F 204800      // h1 last, fp32 [16][68]
#define SMEM_BYTES 209152

#define SW128(o) ((o) ^ (((o) >> 3) & 0x70))

__device__ __forceinline__ uint32_t smem_u32(const void* p) {
    uint32_t a;
    asm("{ .reg .u64 t; cvta.to.shared.u64 t, %1; cvt.u32.u64 %0, t; }" : "=r"(a) : "l"(p));
    return a;
}
__device__ __forceinline__ void ldsm4(uint32_t addr, uint32_t r[4]) {
    asm volatile("ldmatrix.sync.aligned.m8n8.x4.shared.b16 {%0,%1,%2,%3}, [%4];"
                 : "=r"(r[0]), "=r"(r[1]), "=r"(r[2]), "=r"(r[3]) : "r"(addr));
}
__device__ __forceinline__ void mma_f16(float d[4], const uint32_t a[4],
                                        uint32_t b0, uint32_t b1) {
    asm("mma.sync.aligned.m16n8k16.row.col.f32.f16.f16.f32 "
        "{%0,%1,%2,%3}, {%4,%5,%6,%7}, {%8,%9}, {%0,%1,%2,%3};"
        : "+f"(d[0]), "+f"(d[1]), "+f"(d[2]), "+f"(d[3])
        : "r"(a[0]), "r"(a[1]), "r"(a[2]), "r"(a[3]), "r"(b0), "r"(b1));
}
__device__ __forceinline__ float sigf(float v) {
    return __fdividef(1.0f, 1.0f + __expf(-v));
}
__device__ __forceinline__ float tanhf_(float v) {
    float e = __expf(-2.0f * fabsf(v));
    return copysignf(__fdividef(1.0f - e, 1.0f + e), v);
}

// One layer-half MMA pass: 4 k-chunks, A fp16 (unsplit), W hi/lo 2-product
#define MMA_PASS(Abase, WH, WL)                                                  \
    _Pragma("unroll")                                                            \
    for (int kc = 0; kc < 4; ++kc) {                                             \
        uint32_t colA = ((uint32_t)(kc * 32) + aK2) ^ swz;                       \
        uint32_t colB = ((uint32_t)(kc * 32) + bK2) ^ swz;                       \
        uint32_t a[4], bh[4], bl[4];                                             \
        ldsm4((Abase) + aRow + colA, a);                                         \
        ldsm4((WH) + bRow + colB, bh);                                           \
        ldsm4((WL) + bRow + colB, bl);                                           \
        mma_f16(d[0], a, bh[0], bh[1]); mma_f16(d[0], a, bl[0], bl[1]);          \
        mma_f16(d[1], a, bh[2], bh[3]); mma_f16(d[1], a, bl[2], bl[3]);          \
        ldsm4((WH) + 2048 + bRow + colB, bh);                                    \
        ldsm4((WL) + 2048 + bRow + colB, bl);                                    \
        mma_f16(d[2], a, bh[0], bh[1]); mma_f16(d[2], a, bl[0], bl[1]);          \
        mma_f16(d[3], a, bh[2], bh[3]); mma_f16(d[3], a, bl[2], bl[3]);          \
    }

__global__ __launch_bounds__(NTHR, 1)
void lstm_mma_kernel(const float* __restrict__ x,
                     const float* __restrict__ Wih0, const float* __restrict__ Whh0,
                     const float* __restrict__ bih0, const float* __restrict__ bhh0,
                     const float* __restrict__ Wih1, const float* __restrict__ Whh1,
                     const float* __restrict__ bih1, const float* __restrict__ bhh1,
                     const float* __restrict__ fcw,  const float* __restrict__ fcb,
                     float* __restrict__ out)
{
    extern __shared__ char smem[];
    const uint32_t sb = smem_u32(smem);
    const int tid = threadIdx.x, warp = tid >> 5, lane = tid & 31;
    const int r8 = lane & 7, mid = lane >> 3;

    // ldmatrix lane-address components (identical scheme to R7, SW128, 128B rows)
    const uint32_t swz  = (uint32_t)(r8 << 4);
    const uint32_t aRow = (uint32_t)((r8 + ((mid & 1) << 3)) * 128);
    const uint32_t aK2  = (uint32_t)((mid & 2) << 3);
    const uint32_t bRow = (uint32_t)((r8 + ((mid & 2) << 2)) * 128);
    const uint32_t bK2  = (uint32_t)((mid & 1) << 4);

    // ---- weights -> SMEM, fp16 hi/lo, gate-interleaved col n' = cell*4+gate ----
    for (int idx = tid; idx < 256 * 64; idx += NTHR) {
        int np = idx >> 6, k = idx & 63;
        int cell = np >> 2, g = np & 3;
        float v = Whh0[(g * 64 + cell) * 64 + k];
        __half hi = __float2half_rn(v);
        __half lo = __float2half_rn(v - __half2float(hi));
        uint32_t off = SW128((uint32_t)(np * 128 + k * 2));
        *(__half*)(smem + OFF_W0H + off) = hi;
        *(__half*)(smem + OFF_W0L + off) = lo;
    }
    for (int idx = tid; idx < 2 * 256 * 64; idx += NTHR) {
        int blk = idx >> 14, rem = idx & 16383;
        int np = rem >> 6, k = rem & 63;
        int cell = np >> 2, g = np & 3;
        float v = blk ? Whh1[(g * 64 + cell) * 64 + k] : Wih1[(g * 64 + cell) * 64 + k];
        __half hi = __float2half_rn(v);
        __half lo = __float2half_rn(v - __half2float(hi));
        uint32_t off = (uint32_t)(blk * 32768) + SW128((uint32_t)(np * 128 + k * 2));
        *(__half*)(smem + OFF_W1H + off) = hi;
        *(__half*)(smem + OFF_W1L + off) = lo;
    }
    // zero h tiles (A0 x2 + A1 = 6KB)
    for (int idx = tid; idx < 6144 / 4; idx += NTHR)
        ((uint32_t*)(smem + OFF_A0))[idx] = 0;

    // ---- per-lane cell assignment and constants ----
    // lane's n8-tile col pair: nc0 = (lane&3)*2; cell-bit cbit=(lane>>1)&1; gate pair = lane&1
    const int cbit = (lane >> 1) & 1;
    const int m = (lane >> 2) + ((lane & 1) << 3);   // this lane's batch row
    int ct[4];
    float b0a[4][4], w0a[4][4], b1a[4][4];
#pragma unroll
    for (int nt = 0; nt < 4; ++nt) {
        ct[nt] = warp * 8 + nt * 2 + cbit;
#pragma unroll
        for (int g = 0; g < 4; ++g) {
            b0a[nt][g] = bih0[g * 64 + ct[nt]] + bhh0[g * 64 + ct[nt]];
            w0a[nt][g] = Wih0[g * 64 + ct[nt]];
            b1a[nt][g] = bih1[g * 64 + ct[nt]] + bhh1[g * 64 + ct[nt]];
        }
    }
    float c0[4] = {0.f, 0.f, 0.f, 0.f}, c1[4] = {0.f, 0.f, 0.f, 0.f};

    const uint32_t uW0H = sb + OFF_W0H + warp * 4096;
    const uint32_t uW0L = sb + OFF_W0L + warp * 4096;
    const uint32_t uW1H = sb + OFF_W1H + warp * 4096;
    const uint32_t uW1L = sb + OFF_W1L + warp * 4096;
    float* xs = (float*)(smem + OFF_XS);
    const int gRow = blockIdx.x * 16;
    const bool odd = lane & 1;

    __syncthreads();

    for (int s = 0; s < SEQ; ++s) {
        if ((s & 31) == 0) {   // refill x chunk: xs[sc][m] = x[gRow+m][s+sc]
            for (int q = tid; q < 512; q += NTHR)
                xs[q] = x[(size_t)(gRow + (q & 15)) * SEQ + s + (q >> 4)];
            __syncthreads();
        }
        const int rb = s & 1;
        const uint32_t A0r = sb + OFF_A0 + rb * 2048;         // h0(s-1)
        const uint32_t A0w = sb + OFF_A0 + (1 - rb) * 2048;   // h0(s) dest
        const uint32_t A1  = sb + OFF_A1;

        // ================= layer 0 MMA: D = h0(s-1) @ Whh0'^T =================
        float d[4][4];
#pragma unroll
        for (int t = 0; t < 4; ++t) d[t][0] = d[t][1] = d[t][2] = d[t][3] = 0.f;
        MMA_PASS(A0r, uW0H, uW0L);

        // ---- layer 0 epilogue: shfl regroup, cell update, h0 -> A0w ----
        {
            const float xi = xs[(s & 31) * 16 + m];
#pragma unroll
            for (int nt = 0; nt < 4; ++nt) {
                float s1 = odd ? d[nt][0] : d[nt][2];
                float s2 = odd ? d[nt][1] : d[nt][3];
                float r1 = __shfl_xor_sync(0xFFFFFFFFu, s1, 1);
                float r2 = __shfl_xor_sync(0xFFFFFFFFu, s2, 1);
                float gi = odd ? r1 : d[nt][0];
                float gf = odd ? r2 : d[nt][1];
                float gg = odd ? d[nt][2] : r1;
                float go = odd ? d[nt][3] : r2;
                gi += b0a[nt][0] + w0a[nt][0] * xi;
                gf += b0a[nt][1] + w0a[nt][1] * xi;
                gg += b0a[nt][2] + w0a[nt][2] * xi;
                go += b0a[nt][3] + w0a[nt][3] * xi;
                float ii = sigf(gi), ff = sigf(gf), tg = tanhf_(gg), oo = sigf(go);
                c0[nt] = ff * c0[nt] + ii * tg;
                float h = oo * tanhf_(c0[nt]);
                uint32_t off = (uint32_t)(m * 128 + ct[nt] * 2) ^ (uint32_t)((m & 7) << 4);
                *(__half*)(smem + (A0w - sb) + off) = __float2half_rn(h);
            }
        }
        __syncthreads();   // h0(s) visible; also orders h1(s-1) stores before L1 reads

        // ===== layer 1 MMA: D = h0(s) @ Wih1'^T + h1(s-1) @ Whh1'^T =====
#pragma unroll
        for (int t = 0; t < 4; ++t) d[t][0] = d[t][1] = d[t][2] = d[t][3] = 0.f;
        MMA_PASS(A0w, uW1H, uW1L);
        MMA_PASS(A1, uW1H + 32768, uW1L + 32768);
        __syncthreads();   // WAR: all h1(s-1) reads done before overwrite

        // ---- layer 1 epilogue: cell update, h1 -> A1 ----
        {
#pragma unroll
            for (int nt = 0; nt < 4; ++nt) {
                float s1 = odd ? d[nt][0] : d[nt][2];
                float s2 = odd ? d[nt][1] : d[nt][3];
                float r1 = __shfl_xor_sync(0xFFFFFFFFu, s1, 1);
                float r2 = __shfl_xor_sync(0xFFFFFFFFu, s2, 1);
                float gi = odd ? r1 : d[nt][0];
                float gf = odd ? r2 : d[nt][1];
                float gg = odd ? d[nt][2] : r1;
                float go = odd ? d[nt][3] : r2;
                gi += b1a[nt][0];
                gf += b1a[nt][1];
                gg += b1a[nt][2];
                go += b1a[nt][3];
                float ii = sigf(gi), ff = sigf(gf), tg = tanhf_(gg), oo = sigf(go);
                c1[nt] = ff * c1[nt] + ii * tg;
                float h = oo * tanhf_(c1[nt]);
                uint32_t off = (uint32_t)(m * 128 + ct[nt] * 2) ^ (uint32_t)((m & 7) << 4);
                *(__half*)(smem + OFF_A1 + off) = __float2half_rn(h);
                if (s == SEQ - 1)
                    ((float*)(smem + OFF_H1F))[m * 68 + ct[nt]] = h;
            }
        }
        // next step's L0 MMA reads A0w/A0r only; h1 stores covered by next barrier 1
    }

    __syncthreads();

    // ================= final FC: out = h1(S-1) @ fcw^T + fcb =================
    const float* h1f = (const float*)(smem + OFF_H1F);
    for (int idx = tid; idx < 16 * OUTF; idx += NTHR) {
        int r = idx / OUTF, o = idx - r * OUTF;
        float acc = fcb[o];
#pragma unroll 16
        for (int k = 0; k < 64; ++k)
            acc = fmaf(h1f[r * 68 + k], fcw[o * 64 + k], acc);
        out[(gRow + r) * OUTF + o] = acc;
    }
}

extern "C" void kernel_launch(void* const* d_in, const int* in_sizes, int n_in,
                              void* d_out, int out_size)
{
    (void)in_sizes; (void)n_in; (void)out_size;
    cudaFuncSetAttribute(lstm_mma_kernel,
                         cudaFuncAttributeMaxDynamicSharedMemorySize, SMEM_BYTES);
    lstm_mma_kernel<<<NCTA, NTHR, SMEM_BYTES>>>(
        (const float*)d_in[0],  (const float*)d_in[1],  (const float*)d_in[2],
        (const float*)d_in[3],  (const float*)d_in[4],  (const float*)d_in[5],
        (const float*)d_in[6],  (const float*)d_in[7],  (const float*)d_in[8],
        (const float*)d_in[9],  (const float*)d_in[10], (float*)d_out);
}

// round 9
// speedup vs baseline: 6.5828x; 1.8420x over previous
#include <cuda_runtime.h>
#include <cuda_fp16.h>
#include <cstdint>

#define SEQ  512
#define NTHR 256
#define NCTA 128
#define OUTF 72

// ---- SMEM map (bytes) ----
#define OFF_W0  0        // Whh0 fp16 [256 n'][64 k] SW128 (32KB) — dead after prologue
#define OFF_W1  32768    // blk0=Wih1, blk1=Whh1 (+32768) (64KB) — dead after prologue
#define OFF_A0  98304    // h0 fp16 tiles [16 m][64 cell], 2 buffers x 2KB
#define OFF_A1  102400   // h1 fp16 tile (2KB)
#define OFF_XS  104448   // x chunk [32 s][16 m] f32 (2KB)
#define OFF_H1F 106496   // h1 last, fp32 [16][68]
#define SMEM_BYTES 110848

#define SW128(o) ((o) ^ (((o) >> 3) & 0x70))

__device__ __forceinline__ uint32_t smem_u32(const void* p) {
    uint32_t a;
    asm("{ .reg .u64 t; cvta.to.shared.u64 t, %1; cvt.u32.u64 %0, t; }" : "=r"(a) : "l"(p));
    return a;
}
__device__ __forceinline__ void ldsm4(uint32_t addr, uint32_t r[4]) {
    asm volatile("ldmatrix.sync.aligned.m8n8.x4.shared.b16 {%0,%1,%2,%3}, [%4];"
                 : "=r"(r[0]), "=r"(r[1]), "=r"(r[2]), "=r"(r[3]) : "r"(addr));
}
__device__ __forceinline__ void mma_f16(float d[4], const uint32_t a[4],
                                        uint32_t b0, uint32_t b1) {
    asm("mma.sync.aligned.m16n8k16.row.col.f32.f16.f16.f32 "
        "{%0,%1,%2,%3}, {%4,%5,%6,%7}, {%8,%9}, {%0,%1,%2,%3};"
        : "+f"(d[0]), "+f"(d[1]), "+f"(d[2]), "+f"(d[3])
        : "r"(a[0]), "r"(a[1]), "r"(a[2]), "r"(a[3]), "r"(b0), "r"(b1));
}
__device__ __forceinline__ float tanha(float x) {
    float y; asm("tanh.approx.f32 %0, %1;" : "=f"(y) : "f"(x)); return y;
}

__global__ __launch_bounds__(NTHR, 1)
void lstm_mma_kernel(const float* __restrict__ x,
                     const float* __restrict__ Wih0, const float* __restrict__ Whh0,
                     const float* __restrict__ bih0, const float* __restrict__ bhh0,
                     const float* __restrict__ Wih1, const float* __restrict__ Whh1,
                     const float* __restrict__ bih1, const float* __restrict__ bhh1,
                     const float* __restrict__ fcw,  const float* __restrict__ fcb,
                     float* __restrict__ out)
{
    extern __shared__ char smem[];
    const uint32_t sb = smem_u32(smem);
    const int tid = threadIdx.x, warp = tid >> 5, lane = tid & 31;
    const int r8 = lane & 7, mid = lane >> 3;

    // ldmatrix lane-address components (SW128, 128B rows) — proven in R7/R8
    const uint32_t swz  = (uint32_t)(r8 << 4);
    const uint32_t aRow = (uint32_t)((r8 + ((mid & 1) << 3)) * 128);
    const uint32_t aK2  = (uint32_t)((mid & 2) << 3);
    const uint32_t bRow = (uint32_t)((r8 + ((mid & 2) << 2)) * 128);
    const uint32_t bK2  = (uint32_t)((mid & 1) << 4);

    // ---- weights -> SMEM, single fp16, gate-interleaved col n' = cell*4+gate ----
    for (int idx = tid; idx < 256 * 64; idx += NTHR) {
        int np = idx >> 6, k = idx & 63;
        int cell = np >> 2, g = np & 3;
        uint32_t off = SW128((uint32_t)(np * 128 + k * 2));
        *(__half*)(smem + OFF_W0 + off) = __float2half_rn(Whh0[(g * 64 + cell) * 64 + k]);
    }
    for (int idx = tid; idx < 2 * 256 * 64; idx += NTHR) {
        int blk = idx >> 14, rem = idx & 16383;
        int np = rem >> 6, k = rem & 63;
        int cell = np >> 2, g = np & 3;
        float v = blk ? Whh1[(g * 64 + cell) * 64 + k] : Wih1[(g * 64 + cell) * 64 + k];
        uint32_t off = (uint32_t)(blk * 32768) + SW128((uint32_t)(np * 128 + k * 2));
        *(__half*)(smem + OFF_W1 + off) = __float2half_rn(v);
    }
    // zero h tiles (A0 x2 + A1 = 6KB)
    for (int idx = tid; idx < 6144 / 4; idx += NTHR)
        ((uint32_t*)(smem + OFF_A0))[idx] = 0;

    // ---- per-lane cell assignment + biases (0.5-scaled for sigmoid gates) ----
    const int cbit = (lane >> 1) & 1;
    const int m = (lane >> 2) + ((lane & 1) << 3);   // this lane's batch row
    int ct[4];
    float b0a[4][4], w0a[4][4], b1a[4][4];
#pragma unroll
    for (int nt = 0; nt < 4; ++nt) {
        ct[nt] = warp * 8 + nt * 2 + cbit;
#pragma unroll
        for (int g = 0; g < 4; ++g) {
            float sc = (g == 2) ? 1.0f : 0.5f;       // g-gate (tanh) unscaled
            b0a[nt][g] = sc * (bih0[g * 64 + ct[nt]] + bhh0[g * 64 + ct[nt]]);
            w0a[nt][g] = sc * Wih0[g * 64 + ct[nt]];
            b1a[nt][g] = sc * (bih1[g * 64 + ct[nt]] + bhh1[g * 64 + ct[nt]]);
        }
    }
    float c0[4] = {0.f, 0.f, 0.f, 0.f}, c1[4] = {0.f, 0.f, 0.f, 0.f};

    float* xs = (float*)(smem + OFF_XS);
    const int gRow = blockIdx.x * 16;
    const bool odd = lane & 1;

    __syncthreads();

    // ---- preload ALL weight fragments into registers (stationary across SEQ) ----
    uint32_t fb0[4][8], fb1[2][4][8];
#pragma unroll
    for (int kc = 0; kc < 4; ++kc) {
        uint32_t colB = ((uint32_t)(kc * 32) + bK2) ^ swz;
        uint32_t w0b = sb + OFF_W0 + (uint32_t)(warp * 4096) + bRow + colB;
        ldsm4(w0b,        &fb0[kc][0]);
        ldsm4(w0b + 2048, &fb0[kc][4]);
#pragma unroll
        for (int blk = 0; blk < 2; ++blk) {
            uint32_t w1b = sb + OFF_W1 + (uint32_t)(blk * 32768 + warp * 4096) + bRow + colB;
            ldsm4(w1b,        &fb1[blk][kc][0]);
            ldsm4(w1b + 2048, &fb1[blk][kc][4]);
        }
    }

    for (int s = 0; s < SEQ; ++s) {
        if ((s & 31) == 0) {   // refill x chunk: xs[sc][m] = x[gRow+m][s+sc]
            __syncthreads();   // all XS readers of the previous chunk are done
            for (int q = tid; q < 512; q += NTHR)
                xs[q] = x[(size_t)(gRow + (q & 15)) * SEQ + s + (q >> 4)];
            __syncthreads();
        }
        const int rb = s & 1;
        const uint32_t A0r = sb + OFF_A0 + (uint32_t)(rb * 2048);         // h0(s-1)
        const uint32_t A0w = sb + OFF_A0 + (uint32_t)((1 - rb) * 2048);   // h0(s)
        const uint32_t A1  = sb + OFF_A1;

        // ================= layer 0 MMA: D = h0(s-1) @ Whh0'^T =================
        float d[4][4];
#pragma unroll
        for (int t = 0; t < 4; ++t) d[t][0] = d[t][1] = d[t][2] = d[t][3] = 0.f;
#pragma unroll
        for (int kc = 0; kc < 4; ++kc) {
            uint32_t a[4];
            ldsm4(A0r + aRow + ((((uint32_t)(kc * 32)) + aK2) ^ swz), a);
            mma_f16(d[0], a, fb0[kc][0], fb0[kc][1]);
            mma_f16(d[1], a, fb0[kc][2], fb0[kc][3]);
            mma_f16(d[2], a, fb0[kc][4], fb0[kc][5]);
            mma_f16(d[3], a, fb0[kc][6], fb0[kc][7]);
        }
        // ---- layer 0 epilogue: shfl regroup, tanh.approx cell update ----
        {
            const float xi = xs[(s & 31) * 16 + m];
#pragma unroll
            for (int nt = 0; nt < 4; ++nt) {
                float s1 = odd ? d[nt][0] : d[nt][2];
                float s2 = odd ? d[nt][1] : d[nt][3];
                float r1 = __shfl_xor_sync(0xFFFFFFFFu, s1, 1);
                float r2 = __shfl_xor_sync(0xFFFFFFFFu, s2, 1);
                float gi = odd ? r1 : d[nt][0];
                float gf = odd ? r2 : d[nt][1];
                float gg = odd ? d[nt][2] : r1;
                float go = odd ? d[nt][3] : r2;
                float vi = fmaf(gi, 0.5f, fmaf(w0a[nt][0], xi, b0a[nt][0]));
                float vf = fmaf(gf, 0.5f, fmaf(w0a[nt][1], xi, b0a[nt][1]));
                float vg = gg + fmaf(w0a[nt][2], xi, b0a[nt][2]);
                float vo = fmaf(go, 0.5f, fmaf(w0a[nt][3], xi, b0a[nt][3]));
                float ii = fmaf(tanha(vi), 0.5f, 0.5f);
                float ff = fmaf(tanha(vf), 0.5f, 0.5f);
                float tg = tanha(vg);
                float oo = fmaf(tanha(vo), 0.5f, 0.5f);
                c0[nt] = fmaf(ff, c0[nt], ii * tg);
                float h = oo * tanha(c0[nt]);
                uint32_t off = (uint32_t)(m * 128 + ct[nt] * 2) ^ (uint32_t)((m & 7) << 4);
                *(__half*)(smem + (A0w - sb) + off) = __float2half_rn(h);
            }
        }
        __syncthreads();   // h0(s) visible; h1(s-1) stores ordered before L1 reads

        // ===== layer 1 MMA: D = h0(s) @ Wih1'^T + h1(s-1) @ Whh1'^T =====
#pragma unroll
        for (int t = 0; t < 4; ++t) d[t][0] = d[t][1] = d[t][2] = d[t][3] = 0.f;
#pragma unroll
        for (int kc = 0; kc < 4; ++kc) {
            uint32_t colA = (((uint32_t)(kc * 32)) + aK2) ^ swz;
            uint32_t a[4];
            ldsm4(A0w + aRow + colA, a);
            mma_f16(d[0], a, fb1[0][kc][0], fb1[0][kc][1]);
            mma_f16(d[1], a, fb1[0][kc][2], fb1[0][kc][3]);
            mma_f16(d[2], a, fb1[0][kc][4], fb1[0][kc][5]);
            mma_f16(d[3], a, fb1[0][kc][6], fb1[0][kc][7]);
            uint32_t b[4];
            ldsm4(A1 + aRow + colA, b);
            mma_f16(d[0], b, fb1[1][kc][0], fb1[1][kc][1]);
            mma_f16(d[1], b, fb1[1][kc][2], fb1[1][kc][3]);
            mma_f16(d[2], b, fb1[1][kc][4], fb1[1][kc][5]);
            mma_f16(d[3], b, fb1[1][kc][6], fb1[1][kc][7]);
        }
        __syncthreads();   // WAR: all h1(s-1) reads done before overwrite

        // ---- layer 1 epilogue ----
        {
#pragma unroll
            for (int nt = 0; nt < 4; ++nt) {
                float s1 = odd ? d[nt][0] : d[nt][2];
                float s2 = odd ? d[nt][1] : d[nt][3];
                float r1 = __shfl_xor_sync(0xFFFFFFFFu, s1, 1);
                float r2 = __shfl_xor_sync(0xFFFFFFFFu, s2, 1);
                float gi = odd ? r1 : d[nt][0];
                float gf = odd ? r2 : d[nt][1];
                float gg = odd ? d[nt][2] : r1;
                float go = odd ? d[nt][3] : r2;
                float vi = fmaf(gi, 0.5f, b1a[nt][0]);
                float vf = fmaf(gf, 0.5f, b1a[nt][1]);
                float vg = gg + b1a[nt][2];
                float vo = fmaf(go, 0.5f, b1a[nt][3]);
                float ii = fmaf(tanha(vi), 0.5f, 0.5f);
                float ff = fmaf(tanha(vf), 0.5f, 0.5f);
                float tg = tanha(vg);
                float oo = fmaf(tanha(vo), 0.5f, 0.5f);
                c1[nt] = fmaf(ff, c1[nt], ii * tg);
                float h = oo * tanha(c1[nt]);
                uint32_t off = (uint32_t)(m * 128 + ct[nt] * 2) ^ (uint32_t)((m & 7) << 4);
                *(__half*)(smem + OFF_A1 + off) = __float2half_rn(h);
                if (s == SEQ - 1)
                    ((float*)(smem + OFF_H1F))[m * 68 + ct[nt]] = h;
            }
        }
    }

    __syncthreads();

    // ================= final FC: out = h1(S-1) @ fcw^T + fcb =================
    const float* h1f = (const float*)(smem + OFF_H1F);
    for (int idx = tid; idx < 16 * OUTF; idx += NTHR) {
        int r = idx / OUTF, o = idx - r * OUTF;
        float acc = fcb[o];
#pragma unroll 16
        for (int k = 0; k < 64; ++k)
            acc = fmaf(h1f[r * 68 + k], fcw[o * 64 + k], acc);
        out[(gRow + r) * OUTF + o] = acc;
    }
}

extern "C" void kernel_launch(void* const* d_in, const int* in_sizes, int n_in,
                              void* d_out, int out_size)
{
    (void)in_sizes; (void)n_in; (void)out_size;
    cudaFuncSetAttribute(lstm_mma_kernel,
                         cudaFuncAttributeMaxDynamicSharedMemorySize, SMEM_BYTES);
    lstm_mma_kernel<<<NCTA, NTHR, SMEM_BYTES>>>(
        (const float*)d_in[0],  (const float*)d_in[1],  (const float*)d_in[2],
        (const float*)d_in[3],  (const float*)d_in[4],  (const float*)d_in[5],
        (const float*)d_in[6],  (const float*)d_in[7],  (const float*)d_in[8],
        (const float*)d_in[9],  (const float*)d_in[10], (float*)d_out);
}

// round 10
// speedup vs baseline: 7.4616x; 1.1335x over previous
#include <cuda_runtime.h>
#include <cuda_fp16.h>
#include <cstdint>

#define SEQ  512
#define NTHR 512
#define NCTA 128
#define OUTF 72

// ---- SMEM map (bytes) ----
#define OFF_W0  0        // Whh0 fp16 [256 n'][64 k] SW128 (32KB) — dead after prologue
#define OFF_W1  32768    // blk0=Wih1, blk1=Whh1 (+32768) (64KB) — dead after prologue
#define OFF_A0  98304    // h0 fp16 tile [16 m][64 cell], 2 buffers x 2KB
#define OFF_A1  102400   // h1 fp16 tile, 2 buffers x 2KB
#define OFF_XS  106496   // x chunk [32 s][16 m] f32 (2KB)
#define OFF_H1F 108544   // h1 last, fp32 [16][68]
#define SMEM_BYTES 112896

#define SW128(o) ((o) ^ (((o) >> 3) & 0x70))

__device__ __forceinline__ uint32_t smem_u32(const void* p) {
    uint32_t a;
    asm("{ .reg .u64 t; cvta.to.shared.u64 t, %1; cvt.u32.u64 %0, t; }" : "=r"(a) : "l"(p));
    return a;
}
__device__ __forceinline__ void ldsm4(uint32_t addr, uint32_t r[4]) {
    asm volatile("ldmatrix.sync.aligned.m8n8.x4.shared.b16 {%0,%1,%2,%3}, [%4];"
                 : "=r"(r[0]), "=r"(r[1]), "=r"(r[2]), "=r"(r[3]) : "r"(addr));
}
__device__ __forceinline__ void mma_f16(float d[4], const uint32_t a[4],
                                        uint32_t b0, uint32_t b1) {
    asm("mma.sync.aligned.m16n8k16.row.col.f32.f16.f16.f32 "
        "{%0,%1,%2,%3}, {%4,%5,%6,%7}, {%8,%9}, {%0,%1,%2,%3};"
        : "+f"(d[0]), "+f"(d[1]), "+f"(d[2]), "+f"(d[3])
        : "r"(a[0]), "r"(a[1]), "r"(a[2]), "r"(a[3]), "r"(b0), "r"(b1));
}
__device__ __forceinline__ float tanha(float x) {
    float y; asm("tanh.approx.f32 %0, %1;" : "=f"(y) : "f"(x)); return y;
}

// regroup the 4 gate partials of one n8 tile across the (lane, lane^1) pair,
// then do the cell update. b[] pre-scaled (0.5 on sigmoid gates). Returns h.
__device__ __forceinline__ float cellup(const float dd[4], bool odd,
                                        const float b[4], float wx_i, float wx_f,
                                        float wx_g, float wx_o, float& c)
{
    float s1 = odd ? dd[0] : dd[2];
    float s2 = odd ? dd[1] : dd[3];
    float r1 = __shfl_xor_sync(0xFFFFFFFFu, s1, 1);
    float r2 = __shfl_xor_sync(0xFFFFFFFFu, s2, 1);
    float gi = odd ? r1 : dd[0];
    float gf = odd ? r2 : dd[1];
    float gg = odd ? dd[2] : r1;
    float go = odd ? dd[3] : r2;
    float vi = fmaf(gi, 0.5f, b[0] + wx_i);
    float vf = fmaf(gf, 0.5f, b[1] + wx_f);
    float vg = gg + b[2] + wx_g;
    float vo = fmaf(go, 0.5f, b[3] + wx_o);
    float ii = fmaf(tanha(vi), 0.5f, 0.5f);
    float ff = fmaf(tanha(vf), 0.5f, 0.5f);
    float tg = tanha(vg);
    float oo = fmaf(tanha(vo), 0.5f, 0.5f);
    c = fmaf(ff, c, ii * tg);
    return oo * tanha(c);
}

__global__ __launch_bounds__(NTHR, 1)
void lstm_mma_kernel(const float* __restrict__ x,
                     const float* __restrict__ Wih0, const float* __restrict__ Whh0,
                     const float* __restrict__ bih0, const float* __restrict__ bhh0,
                     const float* __restrict__ Wih1, const float* __restrict__ Whh1,
                     const float* __restrict__ bih1, const float* __restrict__ bhh1,
                     const float* __restrict__ fcw,  const float* __restrict__ fcb,
                     float* __restrict__ out)
{
    extern __shared__ char smem[];
    const uint32_t sb = smem_u32(smem);
    const int tid = threadIdx.x, warp = tid >> 5, lane = tid & 31;
    const int r8 = lane & 7, mid = lane >> 3;

    // ldmatrix lane-address components (SW128, 128B rows) — proven R7-R9
    const uint32_t swz  = (uint32_t)(r8 << 4);
    const uint32_t aRow = (uint32_t)((r8 + ((mid & 1) << 3)) * 128);
    const uint32_t aK2  = (uint32_t)((mid & 2) << 3);
    const uint32_t bRow = (uint32_t)((r8 + ((mid & 2) << 2)) * 128);
    const uint32_t bK2  = (uint32_t)((mid & 1) << 4);

    // ---- weights -> SMEM, fp16, gate-interleaved col n' = cell*4+gate ----
    for (int idx = tid; idx < 256 * 64; idx += NTHR) {
        int np = idx >> 6, k = idx & 63;
        int cell = np >> 2, g = np & 3;
        uint32_t off = SW128((uint32_t)(np * 128 + k * 2));
        *(__half*)(smem + OFF_W0 + off) = __float2half_rn(Whh0[(g * 64 + cell) * 64 + k]);
    }
    for (int idx = tid; idx < 2 * 256 * 64; idx += NTHR) {
        int blk = idx >> 14, rem = idx & 16383;
        int np = rem >> 6, k = rem & 63;
        int cell = np >> 2, g = np & 3;
        float v = blk ? Whh1[(g * 64 + cell) * 64 + k] : Wih1[(g * 64 + cell) * 64 + k];
        uint32_t off = (uint32_t)(blk * 32768) + SW128((uint32_t)(np * 128 + k * 2));
        *(__half*)(smem + OFF_W1 + off) = __float2half_rn(v);
    }
    // zero h tiles (A0 x2 + A1 x2 = 8KB)
    for (int idx = tid; idx < 8192 / 4; idx += NTHR)
        ((uint32_t*)(smem + OFF_A0))[idx] = 0;

    // ---- per-lane cell assignment (2 n8 tiles per warp) + constants ----
    const int cbit = (lane >> 1) & 1;
    const int m = (lane >> 2) + ((lane & 1) << 3);   // this lane's batch row
    const bool odd = lane & 1;
    int ct[2];
    float b0a[2][4], w0a[2][4], b1a[2][4];
#pragma unroll
    for (int t = 0; t < 2; ++t) {
        ct[t] = warp * 4 + t * 2 + cbit;
#pragma unroll
        for (int g = 0; g < 4; ++g) {
            float sc = (g == 2) ? 1.0f : 0.5f;       // g-gate (tanh) unscaled
            b0a[t][g] = sc * (bih0[g * 64 + ct[t]] + bhh0[g * 64 + ct[t]]);
            w0a[t][g] = sc * Wih0[g * 64 + ct[t]];
            b1a[t][g] = sc * (bih1[g * 64 + ct[t]] + bhh1[g * 64 + ct[t]]);
        }
    }
    float c0[2] = {0.f, 0.f}, c1[2] = {0.f, 0.f};

    float* xs = (float*)(smem + OFF_XS);
    const int gRow = blockIdx.x * 16;

    // prologue x chunk [0..31]
    if (tid < 512) xs[tid] = x[(size_t)(gRow + (tid & 15)) * SEQ + (tid >> 4)];
    __syncthreads();

    // ---- preload weight fragments (warp owns 16 n'-cols at byte base warp*2048) ----
    uint32_t f0[4][4], f1[2][4][4];
#pragma unroll
    for (int kc = 0; kc < 4; ++kc) {
        uint32_t colB = ((uint32_t)(kc * 32) + bK2) ^ swz;
        ldsm4(sb + OFF_W0 + (uint32_t)(warp * 2048) + bRow + colB, f0[kc]);
#pragma unroll
        for (int blk = 0; blk < 2; ++blk)
            ldsm4(sb + OFF_W1 + (uint32_t)(blk * 32768 + warp * 2048) + bRow + colB,
                  f1[blk][kc]);
    }

    // ---- prologue epilogue: h0(0) = f(x(0)) with zero recurrent term -> A0 buf0 ----
    {
        const float xi = xs[m];                     // x(0) for row m
        const float zero4[4] = {0.f, 0.f, 0.f, 0.f};
#pragma unroll
        for (int t = 0; t < 2; ++t) {
            float h = cellup(zero4, odd, b0a[t],
                             w0a[t][0] * xi, w0a[t][1] * xi, w0a[t][2] * xi, w0a[t][3] * xi,
                             c0[t]);
            uint32_t off = (uint32_t)(m * 128 + ct[t] * 2) ^ (uint32_t)((m & 7) << 4);
            *(__half*)(smem + OFF_A0 + off) = __float2half_rn(h);
        }
    }
    __syncthreads();

    // ================= main loop: ONE barrier per step =================
    for (int s = 0; s < SEQ; ++s) {
        // refill x chunk when entering a new 32-block (epi0 below reads x(s+1))
        if (((s + 1) & 31) == 0 && (s + 1) < SEQ) {
            if (tid < 512)
                xs[tid] = x[(size_t)(gRow + (tid & 15)) * SEQ + (s + 1) + (tid >> 4)];
            __syncthreads();
        }
        const int rb = s & 1;
        const uint32_t A0r = sb + OFF_A0 + (uint32_t)(rb * 2048);          // h0(s)
        const uint32_t A1r = sb + OFF_A1 + (uint32_t)(rb * 2048);          // h1(s-1)
        const uint32_t A0w = sb + OFF_A0 + (uint32_t)((1 - rb) * 2048);    // h0(s+1)
        const uint32_t A1w = sb + OFF_A1 + (uint32_t)((1 - rb) * 2048);    // h1(s)

        // ---- merged MMA block: L1(s) and L0(s+1), all inputs available ----
        float d1[2][4], d0[2][4];
#pragma unroll
        for (int t = 0; t < 2; ++t) {
            d1[t][0] = d1[t][1] = d1[t][2] = d1[t][3] = 0.f;
            d0[t][0] = d0[t][1] = d0[t][2] = d0[t][3] = 0.f;
        }
#pragma unroll
        for (int kc = 0; kc < 4; ++kc) {
            uint32_t colA = (((uint32_t)(kc * 32)) + aK2) ^ swz;
            uint32_t a[4], b[4];
            ldsm4(A0r + aRow + colA, a);            // h0(s)
            ldsm4(A1r + aRow + colA, b);            // h1(s-1)
            mma_f16(d1[0], a, f1[0][kc][0], f1[0][kc][1]);   // h0 @ Wih1
            mma_f16(d1[1], a, f1[0][kc][2], f1[0][kc][3]);
            mma_f16(d1[0], b, f1[1][kc][0], f1[1][kc][1]);   // h1 @ Whh1
            mma_f16(d1[1], b, f1[1][kc][2], f1[1][kc][3]);
            mma_f16(d0[0], a, f0[kc][0], f0[kc][1]);         // h0 @ Whh0 (for s+1)
            mma_f16(d0[1], a, f0[kc][2], f0[kc][3]);
        }

        // ---- epilogue L1(s): h1(s) -> A1w ----
#pragma unroll
        for (int t = 0; t < 2; ++t) {
            float h = cellup(d1[t], odd, b1a[t], 0.f, 0.f, 0.f, 0.f, c1[t]);
            uint32_t off = (uint32_t)(m * 128 + ct[t] * 2) ^ (uint32_t)((m & 7) << 4);
            *(__half*)(smem + (A1w - sb) + off) = __float2half_rn(h);
            if (s == SEQ - 1)
                ((float*)(smem + OFF_H1F))[m * 68 + ct[t]] = h;
        }
        // ---- epilogue L0(s+1): h0(s+1) -> A0w (x clamped at the end) ----
        {
            const int sn = (s + 1 < SEQ) ? (s + 1) : s;
            const float xi = xs[(sn & 31) * 16 + m];
#pragma unroll
            for (int t = 0; t < 2; ++t) {
                float h = cellup(d0[t], odd, b0a[t],
                                 w0a[t][0] * xi, w0a[t][1] * xi,
                                 w0a[t][2] * xi, w0a[t][3] * xi, c0[t]);
                uint32_t off = (uint32_t)(m * 128 + ct[t] * 2) ^ (uint32_t)((m & 7) << 4);
                *(__half*)(smem + (A0w - sb) + off) = __float2half_rn(h);
            }
        }
        __syncthreads();   // the one barrier: stores(s) visible before reads(s+1)
    }

    // ================= final FC: out = h1(S-1) @ fcw^T + fcb =================
    const float* h1f = (const float*)(smem + OFF_H1F);
    for (int idx = tid; idx < 16 * OUTF; idx += NTHR) {
        int r = idx / OUTF, o = idx - r * OUTF;
        float acc = fcb[o];
#pragma unroll 16
        for (int k = 0; k < 64; ++k)
            acc = fmaf(h1f[r * 68 + k], fcw[o * 64 + k], acc);
        out[(gRow + r) * OUTF + o] = acc;
    }
}

extern "C" void kernel_launch(void* const* d_in, const int* in_sizes, int n_in,
                              void* d_out, int out_size)
{
    (void)in_sizes; (void)n_in; (void)out_size;
    cudaFuncSetAttribute(lstm_mma_kernel,
                         cudaFuncAttributeMaxDynamicSharedMemorySize, SMEM_BYTES);
    lstm_mma_kernel<<<NCTA, NTHR, SMEM_BYTES>>>(
        (const float*)d_in[0],  (const float*)d_in[1],  (const float*)d_in[2],
        (const float*)d_in[3],  (const float*)d_in[4],  (const float*)d_in[5],
        (const float*)d_in[6],  (const float*)d_in[7],  (const float*)d_in[8],
        (const float*)d_in[9],  (const float*)d_in[10], (float*)d_out);
}

// round 11
// speedup vs baseline: 7.7265x; 1.0355x over previous
#include <cuda_runtime.h>
#include <cuda_fp16.h>
#include <cstdint>

#define SEQ  512
#define NTHR 512
#define NCTA 128
#define OUTF 72

// ---- SMEM map (bytes) ----
#define OFF_W0  0        // Whh0 fp16 [256 n''][64 k] SW128 (32KB) — dead after prologue
#define OFF_W1  32768    // blk0=Wih1, blk1=Whh1 (+32768) (64KB) — dead after prologue
#define OFF_A0  98304    // h0 fp16 tile [16 m][64 cell], 2 buffers x 2KB
#define OFF_A1  102400   // h1 fp16 tile, 2 buffers x 2KB
#define OFF_XS  106496   // x chunk [32 s][16 m] f32 (2KB)
#define OFF_H1F 108544   // h1 last, fp32 [16][68]
#define SMEM_BYTES 112896

#define SW128(o) ((o) ^ (((o) >> 3) & 0x70))

__device__ __forceinline__ uint32_t smem_u32(const void* p) {
    uint32_t a;
    asm("{ .reg .u64 t; cvta.to.shared.u64 t, %1; cvt.u32.u64 %0, t; }" : "=r"(a) : "l"(p));
    return a;
}
__device__ __forceinline__ void ldsm4(uint32_t addr, uint32_t r[4]) {
    asm volatile("ldmatrix.sync.aligned.m8n8.x4.shared.b16 {%0,%1,%2,%3}, [%4];"
                 : "=r"(r[0]), "=r"(r[1]), "=r"(r[2]), "=r"(r[3]) : "r"(addr));
}
__device__ __forceinline__ void mma_f16(float d[4], const uint32_t a[4],
                                        uint32_t b0, uint32_t b1) {
    asm("mma.sync.aligned.m16n8k16.row.col.f32.f16.f16.f32 "
        "{%0,%1,%2,%3}, {%4,%5,%6,%7}, {%8,%9}, {%0,%1,%2,%3};"
        : "+f"(d[0]), "+f"(d[1]), "+f"(d[2]), "+f"(d[3])
        : "r"(a[0]), "r"(a[1]), "r"(a[2]), "r"(a[3]), "r"(b0), "r"(b1));
}
__device__ __forceinline__ float tanha(float x) {
    float y; asm("tanh.approx.f32 %0, %1;" : "=f"(y) : "f"(x)); return y;
}

// In-lane cell update: raw gate pre-activations (MMA partials), pre-scaled
// biases b[] (0.5 on sigmoid gates), optional 0.5-scaled x contributions.
__device__ __forceinline__ float cellup(float gi, float gf, float gg, float go,
                                        const float b[4],
                                        float wx0, float wx1, float wx2, float wx3,
                                        float& c)
{
    float vi = fmaf(gi, 0.5f, b[0] + wx0);
    float vf = fmaf(gf, 0.5f, b[1] + wx1);
    float vg = gg + b[2] + wx2;
    float vo = fmaf(go, 0.5f, b[3] + wx3);
    float ii = fmaf(tanha(vi), 0.5f, 0.5f);
    float ff = fmaf(tanha(vf), 0.5f, 0.5f);
    float tg = tanha(vg);
    float oo = fmaf(tanha(vo), 0.5f, 0.5f);
    c = fmaf(ff, c, ii * tg);
    return oo * tanha(c);
}

__global__ __launch_bounds__(NTHR, 1)
void lstm_mma_kernel(const float* __restrict__ x,
                     const float* __restrict__ Wih0, const float* __restrict__ Whh0,
                     const float* __restrict__ bih0, const float* __restrict__ bhh0,
                     const float* __restrict__ Wih1, const float* __restrict__ Whh1,
                     const float* __restrict__ bih1, const float* __restrict__ bhh1,
                     const float* __restrict__ fcw,  const float* __restrict__ fcb,
                     float* __restrict__ out)
{
    extern __shared__ char smem[];
    const uint32_t sb = smem_u32(smem);
    const int tid = threadIdx.x, warp = tid >> 5, lane = tid & 31;
    const int r8 = lane & 7, mid = lane >> 3;

    // ldmatrix lane-address components (SW128, 128B rows) — proven R7-R10
    const uint32_t swz  = (uint32_t)(r8 << 4);
    const uint32_t aRow = (uint32_t)((r8 + ((mid & 1) << 3)) * 128);
    const uint32_t aK2  = (uint32_t)((mid & 2) << 3);
    const uint32_t bRow = (uint32_t)((r8 + ((mid & 2) << 2)) * 128);
    const uint32_t bK2  = (uint32_t)((mid & 1) << 4);

    // ---- weights -> SMEM, fp16, gate-pair-across-tiles layout ----
    // n'' = w*16 + gp*8 + c*2 + g2  ->  gate = gp*2+g2, cell = w*4+c
    for (int idx = tid; idx < 256 * 64; idx += NTHR) {
        int np = idx >> 6, k = idx & 63;
        int w = np >> 4, gp = (np >> 3) & 1, c = (np >> 1) & 3, g2 = np & 1;
        int row = (gp * 2 + g2) * 64 + (w * 4 + c);
        uint32_t off = SW128((uint32_t)(np * 128 + k * 2));
        *(__half*)(smem + OFF_W0 + off) = __float2half_rn(Whh0[row * 64 + k]);
    }
    for (int idx = tid; idx < 2 * 256 * 64; idx += NTHR) {
        int blk = idx >> 14, rem = idx & 16383;
        int np = rem >> 6, k = rem & 63;
        int w = np >> 4, gp = (np >> 3) & 1, c = (np >> 1) & 3, g2 = np & 1;
        int row = (gp * 2 + g2) * 64 + (w * 4 + c);
        float v = blk ? Whh1[row * 64 + k] : Wih1[row * 64 + k];
        uint32_t off = (uint32_t)(blk * 32768) + SW128((uint32_t)(np * 128 + k * 2));
        *(__half*)(smem + OFF_W1 + off) = __float2half_rn(v);
    }
    // zero h tiles (A0 x2 + A1 x2 = 8KB)
    for (int idx = tid; idx < 8192 / 4; idx += NTHR)
        ((uint32_t*)(smem + OFF_A0))[idx] = 0;

    // ---- per-lane assignment: ONE cell, TWO batch rows ----
    const int ct = warp * 4 + (lane & 3);      // this lane's cell
    const int m0 = lane >> 2, m1 = m0 + 8;     // this lane's batch rows
    float b0a[4], w0a[4], b1a[4];
#pragma unroll
    for (int g = 0; g < 4; ++g) {
        float sc = (g == 2) ? 1.0f : 0.5f;     // g-gate (tanh) unscaled
        b0a[g] = sc * (bih0[g * 64 + ct] + bhh0[g * 64 + ct]);
        w0a[g] = sc * Wih0[g * 64 + ct];
        b1a[g] = sc * (bih1[g * 64 + ct] + bhh1[g * 64 + ct]);
    }
    float c0[2] = {0.f, 0.f}, c1[2] = {0.f, 0.f};

    // loop-invariant h-store offsets (same swizzle nibble for m0 and m1)
    const uint32_t hoff0 = (uint32_t)(m0 * 128 + ct * 2) ^ (uint32_t)(m0 << 4);
    const uint32_t hoff1 = hoff0 + 1024;

    float* xs = (float*)(smem + OFF_XS);
    const int gRow = blockIdx.x * 16;

    // prologue x chunk [0..31]
    if (tid < 512) xs[tid] = x[(size_t)(gRow + (tid & 15)) * SEQ + (tid >> 4)];
    __syncthreads();

    // ---- preload weight fragments (warp owns 16 n''-cols at byte base warp*2048) ----
    uint32_t f0[4][4], f1[2][4][4];
#pragma unroll
    for (int kc = 0; kc < 4; ++kc) {
        uint32_t colB = ((uint32_t)(kc * 32) + bK2) ^ swz;
        ldsm4(sb + OFF_W0 + (uint32_t)(warp * 2048) + bRow + colB, f0[kc]);
#pragma unroll
        for (int blk = 0; blk < 2; ++blk)
            ldsm4(sb + OFF_W1 + (uint32_t)(blk * 32768 + warp * 2048) + bRow + colB,
                  f1[blk][kc]);
    }

    // ---- prologue: h0(0) = f(x(0)), zero recurrent term -> A0 buf0 ----
    {
        const float xi0 = xs[m0], xi1 = xs[m1];
        float h;
        h = cellup(0.f, 0.f, 0.f, 0.f, b0a,
                   w0a[0] * xi0, w0a[1] * xi0, w0a[2] * xi0, w0a[3] * xi0, c0[0]);
        *(__half*)(smem + OFF_A0 + hoff0) = __float2half_rn(h);
        h = cellup(0.f, 0.f, 0.f, 0.f, b0a,
                   w0a[0] * xi1, w0a[1] * xi1, w0a[2] * xi1, w0a[3] * xi1, c0[1]);
        *(__half*)(smem + OFF_A0 + hoff1) = __float2half_rn(h);
    }
    __syncthreads();

    // ================= main loop: ONE barrier per step =================
#pragma unroll 2
    for (int s = 0; s < SEQ; ++s) {
        if (((s + 1) & 31) == 0 && (s + 1) < SEQ) {   // refill x for chunk s+1..s+32
            if (tid < 512)
                xs[tid] = x[(size_t)(gRow + (tid & 15)) * SEQ + (s + 1) + (tid >> 4)];
            __syncthreads();
        }
        const int rb = s & 1;
        const uint32_t A0r = sb + OFF_A0 + (uint32_t)(rb * 2048);          // h0(s)
        const uint32_t A1r = sb + OFF_A1 + (uint32_t)(rb * 2048);          // h1(s-1)
        const uint32_t A0w = sb + OFF_A0 + (uint32_t)((1 - rb) * 2048);    // h0(s+1)
        const uint32_t A1w = sb + OFF_A1 + (uint32_t)((1 - rb) * 2048);    // h1(s)

        // ---- merged MMA block: L1(s) [split accumulators] + L0(s+1) ----
        float d0[2][4], d1a[2][4], d1b[2][4];
#pragma unroll
        for (int t = 0; t < 2; ++t)
#pragma unroll
            for (int q = 0; q < 4; ++q) { d0[t][q] = 0.f; d1a[t][q] = 0.f; d1b[t][q] = 0.f; }
#pragma unroll
        for (int kc = 0; kc < 4; ++kc) {
            uint32_t colA = (((uint32_t)(kc * 32)) + aK2) ^ swz;
            uint32_t a[4], b[4];
            ldsm4(A0r + aRow + colA, a);            // h0(s)
            ldsm4(A1r + aRow + colA, b);            // h1(s-1)
            mma_f16(d0[0],  a, f0[kc][0], f0[kc][1]);        // h0 @ Whh0  (s+1)
            mma_f16(d0[1],  a, f0[kc][2], f0[kc][3]);
            mma_f16(d1a[0], a, f1[0][kc][0], f1[0][kc][1]);  // h0 @ Wih1
            mma_f16(d1a[1], a, f1[0][kc][2], f1[0][kc][3]);
            mma_f16(d1b[0], b, f1[1][kc][0], f1[1][kc][1]);  // h1 @ Whh1
            mma_f16(d1b[1], b, f1[1][kc][2], f1[1][kc][3]);
        }

        // ---- epilogue L0(s+1): needs only d0 (4-deep chain, finishes first) ----
        {
            const int sn = (s + 1 < SEQ) ? (s + 1) : s;
            const float xi0 = xs[(sn & 31) * 16 + m0];
            const float xi1 = xs[(sn & 31) * 16 + m1];
            float h;
            h = cellup(d0[0][0], d0[0][1], d0[1][0], d0[1][1], b0a,
                       w0a[0] * xi0, w0a[1] * xi0, w0a[2] * xi0, w0a[3] * xi0, c0[0]);
            *(__half*)(smem + (A0w - sb) + hoff0) = __float2half_rn(h);
            h = cellup(d0[0][2], d0[0][3], d0[1][2], d0[1][3], b0a,
                       w0a[0] * xi1, w0a[1] * xi1, w0a[2] * xi1, w0a[3] * xi1, c0[1]);
            *(__half*)(smem + (A0w - sb) + hoff1) = __float2half_rn(h);
        }
        // ---- epilogue L1(s): gates = d1a + d1b ----
        {
            float h;
            h = cellup(d1a[0][0] + d1b[0][0], d1a[0][1] + d1b[0][1],
                       d1a[1][0] + d1b[1][0], d1a[1][1] + d1b[1][1],
                       b1a, 0.f, 0.f, 0.f, 0.f, c1[0]);
            *(__half*)(smem + (A1w - sb) + hoff0) = __float2half_rn(h);
            if (s == SEQ - 1) ((float*)(smem + OFF_H1F))[m0 * 68 + ct] = h;
            h = cellup(d1a[0][2] + d1b[0][2], d1a[0][3] + d1b[0][3],
                       d1a[1][2] + d1b[1][2], d1a[1][3] + d1b[1][3],
                       b1a, 0.f, 0.f, 0.f, 0.f, c1[1]);
            *(__half*)(smem + (A1w - sb) + hoff1) = __float2half_rn(h);
            if (s == SEQ - 1) ((float*)(smem + OFF_H1F))[m1 * 68 + ct] = h;
        }
        __syncthreads();   // the one barrier: stores(s) visible before reads(s+1)
    }

    // ================= final FC: out = h1(S-1) @ fcw^T + fcb =================
    const float* h1f = (const float*)(smem + OFF_H1F);
    for (int idx = tid; idx < 16 * OUTF; idx += NTHR) {
        int r = idx / OUTF, o = idx - r * OUTF;
        float acc = fcb[o];
#pragma unroll 16
        for (int k = 0; k < 64; ++k)
            acc = fmaf(h1f[r * 68 + k], fcw[o * 64 + k], acc);
        out[(gRow + r) * OUTF + o] = acc;
    }
}

extern "C" void kernel_launch(void* const* d_in, const int* in_sizes, int n_in,
                              void* d_out, int out_size)
{
    (void)in_sizes; (void)n_in; (void)out_size;
    cudaFuncSetAttribute(lstm_mma_kernel,
                         cudaFuncAttributeMaxDynamicSharedMemorySize, SMEM_BYTES);
    lstm_mma_kernel<<<NCTA, NTHR, SMEM_BYTES>>>(
        (const float*)d_in[0],  (const float*)d_in[1],  (const float*)d_in[2],
        (const float*)d_in[3],  (const float*)d_in[4],  (const float*)d_in[5],
        (const float*)d_in[6],  (const float*)d_in[7],  (const float*)d_in[8],
        (const float*)d_in[9],  (const float*)d_in[10], (float*)d_out);
}